// round 6
// baseline (speedup 1.0000x reference)
#include <cuda_runtime.h>
#include <math.h>
#include <stdint.h>

#define TLEN  32000
#define BATCH 8
#define RES   32
#define SKIPC 32
#define TT    128

typedef unsigned long long ull;

// ==================== helpers ==============================================
__device__ __forceinline__ uint32_t smem_u32(const void* p) {
    uint32_t a;
    asm("{ .reg .u64 t; cvta.to.shared.u64 t, %1; cvt.u32.u64 %0, t; }" : "=r"(a) : "l"(p));
    return a;
}
__device__ __forceinline__ void sts32(uint32_t a, uint32_t v) {
    asm volatile("st.shared.b32 [%0], %1;" :: "r"(a), "r"(v));
}
__device__ __forceinline__ void ldsm4(uint32_t& r0, uint32_t& r1, uint32_t& r2, uint32_t& r3,
                                      uint32_t addr) {
    asm volatile("ldmatrix.sync.aligned.m8n8.x4.shared.b16 {%0,%1,%2,%3}, [%4];"
                 : "=r"(r0), "=r"(r1), "=r"(r2), "=r"(r3) : "r"(addr));
}
// pack {lo=v0, hi=v1} as bf16x2 (RN)
__device__ __forceinline__ uint32_t pack_bf16x2(float v0, float v1) {
    uint32_t r;
    asm("cvt.rn.bf16x2.f32 %0, %1, %2;" : "=r"(r) : "f"(v1), "f"(v0));
    return r;
}
// mma.sync m16n8k16 bf16, fp32 accumulate
__device__ __forceinline__ void mma_bf16(float* c,
                                         uint32_t a0, uint32_t a1, uint32_t a2, uint32_t a3,
                                         uint32_t b0, uint32_t b1) {
    asm volatile("mma.sync.aligned.m16n8k16.row.col.f32.bf16.bf16.f32 "
                 "{%0,%1,%2,%3}, {%4,%5,%6,%7}, {%8,%9}, {%0,%1,%2,%3};"
                 : "+f"(c[0]), "+f"(c[1]), "+f"(c[2]), "+f"(c[3])
                 : "r"(a0), "r"(a1), "r"(a2), "r"(a3), "r"(b0), "r"(b1));
}
__device__ __forceinline__ float ftanh(float x) {
    float e = __expf(-2.f * fabsf(x));
    float r = __fdividef(1.f - e, 1.f + e);
    return copysignf(r, x);
}
__device__ __forceinline__ float fsigm(float x) {
    return __fdividef(1.f, 1.f + __expf(-x));
}
// split pair into bf16 hi pack + residual lo pack
__device__ __forceinline__ void split_pair(float v0, float v1, uint32_t& hi, uint32_t& lo) {
    hi = pack_bf16x2(v0, v1);
    float h0 = __uint_as_float((hi & 0xFFFFu) << 16);
    float h1 = __uint_as_float(hi & 0xFFFF0000u);
    lo = pack_bf16x2(v0 - h0, v1 - h1);
}

// ==================== device scratch =======================================
__device__ float g_h0[BATCH * RES * TLEN];
__device__ float g_h1[BATCH * RES * TLEN];
__device__ float g_skip[BATCH * SKIPC * TLEN];
__device__ float g_ts[BATCH * SKIPC * TLEN];
__device__ float g_p2[BATCH * 16 * TLEN];
__device__ float g_p3[BATCH * 8 * TLEN];
__device__ float g_p4[BATCH * 1 * TLEN];

// ==================== front conv ===========================================
__global__ __launch_bounds__(TT) void k_front(const float* __restrict__ x,
                                              const float* __restrict__ w) {
    int b = blockIdx.y;
    int t = blockIdx.x * TT + threadIdx.x;
    if (t >= TLEN) return;
    const float* xb = x + b * TLEN;
    float x0 = xb[t];
    float x1 = (t >= 1) ? xb[t - 1] : 0.f;
    float x2 = (t >= 2) ? xb[t - 2] : 0.f;
#pragma unroll
    for (int oc = 0; oc < RES; oc++) {
        float v = fmaf(w[oc * 3 + 0], x2, fmaf(w[oc * 3 + 1], x1, w[oc * 3 + 2] * x0));
        g_h0[(b * RES + oc) * TLEN + t] = v;
        g_skip[(b * SKIPC + oc) * TLEN + t] = 0.f;
    }
}

// ==================== residual layer via mma.sync + ldmatrix ===============
// SMEM strides chosen conflict-free for ldmatrix (stride/4 mod 32 = 20)
#define STRA 208   // A/B row stride bytes (96 bf16 data + pad)
#define STRG 80    // G/W2 row stride bytes (32 bf16 data + pad)
#define SO_AH 0
#define SO_AL (SO_AH + 128 * STRA)        // 26624
#define SO_BH (SO_AL + 128 * STRA)        // 53248
#define SO_BL (SO_BH + 64 * STRA)         // 66560
#define SO_GH (SO_BL + 64 * STRA)         // 79872
#define SO_GL (SO_GH + 128 * STRG)        // 90112
#define SO_W2H (SO_GL + 128 * STRG)       // 100352
#define SO_W2L (SO_W2H + 64 * STRG)       // 105472
#define SMEM_LAYER_BYTES (SO_W2L + 64 * STRG)  // 110592

// one GEMM pass: D[128x64] += A[128xK]·B[64xK]^T, K = nk16*16, ldmatrix frags
__device__ __forceinline__ void gemm_pass(uint32_t aB, uint32_t bB, int stride,
                                          int nk16, float acc[2][8][4],
                                          int wid, int lid) {
    int lr = lid & 7;
    int aRowOff = lr + ((lid >> 3) & 1) * 8;   // row-in-tile for A matrices
    int aKOff = (lid >> 4) * 8;                // k half
    int bRowOff = lr + (lid >> 4) * 8;         // n-row for B matrices
    int bKOff = ((lid >> 3) & 1) * 8;          // k half
    uint32_t aAddr = aB + (uint32_t)((32 * wid + aRowOff) * stride + aKOff * 2);
    uint32_t bAddr0 = bB + (uint32_t)(bRowOff * stride + bKOff * 2);
#pragma unroll
    for (int k = 0; k < nk16; k++) {
        uint32_t ka = (uint32_t)(k * 32);
        uint32_t a0, a1, a2, a3, c0, c1, c2, c3;
        ldsm4(a0, a1, a2, a3, aAddr + ka);
        ldsm4(c0, c1, c2, c3, aAddr + (uint32_t)(16 * stride) + ka);
#pragma unroll
        for (int np = 0; np < 4; np++) {   // pairs of n8 tiles
            uint32_t b0, b1, b2, b3;
            ldsm4(b0, b1, b2, b3, bAddr0 + (uint32_t)(16 * np * stride) + ka);
            mma_bf16(acc[0][2 * np],     a0, a1, a2, a3, b0, b1);
            mma_bf16(acc[0][2 * np + 1], a0, a1, a2, a3, b2, b3);
            mma_bf16(acc[1][2 * np],     c0, c1, c2, c3, b0, b1);
            mma_bf16(acc[1][2 * np + 1], c0, c1, c2, c3, b2, b3);
        }
    }
}

__global__ __launch_bounds__(TT, 2) void k_layer(const float* __restrict__ hin,
                                                 float* __restrict__ hout,
                                                 const float* __restrict__ w1,  // [64][32][3]
                                                 const float* __restrict__ w2,  // [64][32]
                                                 int d) {
    extern __shared__ __align__(16) char smem[];
    uint32_t sb = smem_u32(smem);
    int tid = threadIdx.x;
    int wid = tid >> 5;
    int lid = tid & 31;
    int qr = lid >> 2;   // 0..7
    int qc = lid & 3;    // 0..3
    int b = blockIdx.y;
    int t0 = blockIdx.x * TT;

    const float* hb = hin + b * RES * TLEN;

    // ---- stage A [128][96] hi/lo: thread = time row m
    {
        int m = tid;
        int t = t0 + m;
        uint32_t rowH = sb + SO_AH + (uint32_t)(m * STRA);
        uint32_t rowL = sb + SO_AL + (uint32_t)(m * STRA);
#pragma unroll
        for (int tap = 0; tap < 3; tap++) {
            int tt = t - (2 - tap) * d;
            bool ok = (tt >= 0);
#pragma unroll
            for (int ic = 0; ic < 32; ic += 2) {
                float v0 = ok ? hb[ic * TLEN + tt] : 0.f;
                float v1 = ok ? hb[(ic + 1) * TLEN + tt] : 0.f;
                uint32_t hi, lo;
                split_pair(v0, v1, hi, lo);
                uint32_t off = (uint32_t)((tap * 32 + ic) * 2);
                sts32(rowH + off, hi);
                sts32(rowL + off, lo);
            }
        }
    }
    // ---- stage B (w1) [64][96] hi/lo
    for (int i = tid; i < 64 * 48; i += TT) {
        int oc = i / 48, pj = i % 48;
        int k0 = 2 * pj;
        int tap = k0 >> 5, ic = k0 & 31;
        float v0 = w1[oc * 96 + ic * 3 + tap];
        float v1 = w1[oc * 96 + (ic + 1) * 3 + tap];
        uint32_t hi, lo;
        split_pair(v0, v1, hi, lo);
        uint32_t off = (uint32_t)(oc * STRA + k0 * 2);
        sts32(sb + SO_BH + off, hi);
        sts32(sb + SO_BL + off, lo);
    }
    // ---- stage W2 [64][32] hi/lo
    for (int i = tid; i < 64 * 16; i += TT) {
        int oc = i / 16, ic = 2 * (i % 16);
        float v0 = w2[oc * 32 + ic];
        float v1 = w2[oc * 32 + ic + 1];
        uint32_t hi, lo;
        split_pair(v0, v1, hi, lo);
        uint32_t off = (uint32_t)(oc * STRG + ic * 2);
        sts32(sb + SO_W2H + off, hi);
        sts32(sb + SO_W2L + off, lo);
    }
    __syncthreads();

    // ---- conv GEMM: 3 passes (AH·BH, AL·BH, AH·BL)
    float acc[2][8][4];
#pragma unroll
    for (int m = 0; m < 2; m++)
#pragma unroll
        for (int n = 0; n < 8; n++)
#pragma unroll
            for (int j = 0; j < 4; j++) acc[m][n][j] = 0.f;

    gemm_pass(sb + SO_AH, sb + SO_BH, STRA, 6, acc, wid, lid);
    gemm_pass(sb + SO_AL, sb + SO_BH, STRA, 6, acc, wid, lid);
    gemm_pass(sb + SO_AH, sb + SO_BL, STRA, 6, acc, wid, lid);

    // ---- gating -> G [128][32] hi/lo in SMEM
#pragma unroll
    for (int m = 0; m < 2; m++) {
#pragma unroll
        for (int rh = 0; rh < 2; rh++) {
            int row = 32 * wid + 16 * m + qr + 8 * rh;
            uint32_t goff = (uint32_t)(row * STRG + 4 * qc);
#pragma unroll
            for (int n = 0; n < 4; n++) {
                float g0 = ftanh(acc[m][n][2 * rh + 0]) * fsigm(acc[m][n + 4][2 * rh + 0]);
                float g1 = ftanh(acc[m][n][2 * rh + 1]) * fsigm(acc[m][n + 4][2 * rh + 1]);
                uint32_t hi, lo;
                split_pair(g0, g1, hi, lo);
                sts32(sb + SO_GH + goff + (uint32_t)(n * 16), hi);
                sts32(sb + SO_GL + goff + (uint32_t)(n * 16), lo);
            }
        }
    }
    __syncthreads();

    // ---- 1x1 GEMM: z[128x64] = G[128x32]·W2[64x32]^T, 3 passes
    float acc2[2][8][4];
#pragma unroll
    for (int m = 0; m < 2; m++)
#pragma unroll
        for (int n = 0; n < 8; n++)
#pragma unroll
            for (int j = 0; j < 4; j++) acc2[m][n][j] = 0.f;

    gemm_pass(sb + SO_GH, sb + SO_W2H, STRG, 2, acc2, wid, lid);
    gemm_pass(sb + SO_GL, sb + SO_W2H, STRG, 2, acc2, wid, lid);
    gemm_pass(sb + SO_GH, sb + SO_W2L, STRG, 2, acc2, wid, lid);

    // ---- epilogue: residual + skip
    float* hob = hout + b * RES * TLEN;
    float* skb = g_skip + b * SKIPC * TLEN;
#pragma unroll
    for (int m = 0; m < 2; m++) {
#pragma unroll
        for (int rh = 0; rh < 2; rh++) {
            int t = t0 + 32 * wid + 16 * m + qr + 8 * rh;
#pragma unroll
            for (int n = 0; n < 4; n++) {
                int c = 8 * n + 2 * qc;
                hob[c * TLEN + t]       = hb[c * TLEN + t] + acc2[m][n][2 * rh + 0];
                hob[(c + 1) * TLEN + t] = hb[(c + 1) * TLEN + t] + acc2[m][n][2 * rh + 1];
            }
#pragma unroll
            for (int n = 4; n < 8; n++) {
                int c = 8 * (n - 4) + 2 * qc;
                skb[c * TLEN + t]       += acc2[m][n][2 * rh + 0];
                skb[(c + 1) * TLEN + t] += acc2[m][n][2 * rh + 1];
            }
        }
    }
}

// ==================== tanh over skip =======================================
__global__ __launch_bounds__(TT) void k_tanhskip() {
    int b = blockIdx.y;
    int t = blockIdx.x * TT + threadIdx.x;
    if (t >= TLEN) return;
#pragma unroll
    for (int c = 0; c < SKIPC; c++) {
        int idx = (b * SKIPC + c) * TLEN + t;
        g_ts[idx] = ftanh(g_skip[idx]);
    }
}

// ==================== generic causal k=3 conv + tanh =======================
template <int IC, int OC>
__global__ __launch_bounds__(TT) void k_conv3tanh(const float* __restrict__ in,
                                                  float* __restrict__ out,
                                                  const float* __restrict__ w) {
    __shared__ float ws[3][IC][OC];
    int tid = threadIdx.x;
    for (int i = tid; i < OC * IC * 3; i += TT) {
        int oc = i / (IC * 3), r = i % (IC * 3), ic = r / 3, k = r % 3;
        ws[k][ic][oc] = w[i];
    }
    __syncthreads();

    int b = blockIdx.y;
    int t = blockIdx.x * TT + tid;
    if (t >= TLEN) return;
    const float* ib = in + b * IC * TLEN;

    float acc[OC];
#pragma unroll
    for (int o = 0; o < OC; o++) acc[o] = 0.f;
#pragma unroll
    for (int k = 0; k < 3; k++) {
        int tt = t - (2 - k);
        if (tt >= 0) {
#pragma unroll
            for (int ic = 0; ic < IC; ic++) {
                float v = ib[ic * TLEN + tt];
#pragma unroll
                for (int o = 0; o < OC; o++)
                    acc[o] = fmaf(v, ws[k][ic][o], acc[o]);
            }
        }
    }
    float* ob = out + b * OC * TLEN;
#pragma unroll
    for (int o = 0; o < OC; o++)
        ob[o * TLEN + t] = ftanh(acc[o]);
}

// ==================== Volterra head ========================================
__global__ __launch_bounds__(TT) void k_vnn(const float* __restrict__ w1,
                                            const float* __restrict__ w2,
                                            float* __restrict__ out) {
    int b = blockIdx.y;
    int t = blockIdx.x * TT + threadIdx.x;
    if (t >= TLEN) return;
    const float* pb = g_p4 + b * TLEN;

    float pv[16];
#pragma unroll
    for (int k = 0; k < 16; k++) {
        int tt = t - (15 - k);
        pv[k] = (tt >= 0) ? pb[tt] : 0.f;
    }
    float lin = 0.f;
#pragma unroll
    for (int k = 0; k < 16; k++) lin = fmaf(w1[k], pv[k], lin);

    float x2[6];
#pragma unroll
    for (int j = 0; j < 6; j++) {
        float a = 0.f;
#pragma unroll
        for (int k = 0; k < 16; k++) a = fmaf(w2[j * 16 + k], pv[k], a);
        x2[j] = a;
    }
    float quad = x2[0] * x2[3] + x2[1] * x2[4] + x2[2] * x2[5];
    out[b * TLEN + t] = lin + quad;
}

// ==================== host launch ==========================================
extern "C" void kernel_launch(void* const* d_in, const int* in_sizes, int n_in,
                              void* d_out, int out_size) {
    const float* x       = (const float*)d_in[0];
    const float* conv1_w = (const float*)d_in[1];
    const float* res_w1  = (const float*)d_in[2];
    const float* res_w2  = (const float*)d_in[3];
    const float* post2_w = (const float*)d_in[4];
    const float* post3_w = (const float*)d_in[5];
    const float* post4_w = (const float*)d_in[6];
    const float* vnn1_w  = (const float*)d_in[7];
    const float* vnn2_w  = (const float*)d_in[8];
    float* out = (float*)d_out;

    float *h0p, *h1p, *tsp, *p2p, *p3p, *p4p;
    cudaGetSymbolAddress((void**)&h0p, g_h0);
    cudaGetSymbolAddress((void**)&h1p, g_h1);
    cudaGetSymbolAddress((void**)&tsp, g_ts);
    cudaGetSymbolAddress((void**)&p2p, g_p2);
    cudaGetSymbolAddress((void**)&p3p, g_p3);
    cudaGetSymbolAddress((void**)&p4p, g_p4);

    cudaFuncSetAttribute(k_layer, cudaFuncAttributeMaxDynamicSharedMemorySize,
                         SMEM_LAYER_BYTES);

    dim3 grid(TLEN / TT, BATCH);   // 250 x 8

    k_front<<<grid, TT>>>(x, conv1_w);

    const float* hin = h0p;
    float* hout = h1p;
    for (int s = 0; s < 2; s++) {
        for (int i = 0; i < 10; i++) {
            k_layer<<<grid, TT, SMEM_LAYER_BYTES>>>(hin, hout,
                                                    res_w1 + (size_t)i * 64 * 32 * 3,
                                                    res_w2 + (size_t)i * 64 * 32,
                                                    1 << i);
            const float* tmp = hout;
            hout = (float*)hin;
            hin = tmp;
        }
    }

    k_tanhskip<<<grid, TT>>>();
    k_conv3tanh<32, 16><<<grid, TT>>>(tsp, p2p, post2_w);
    k_conv3tanh<16, 8><<<grid, TT>>>(p2p, p3p, post3_w);
    k_conv3tanh<8, 1><<<grid, TT>>>(p3p, p4p, post4_w);
    k_vnn<<<grid, TT>>>(vnn1_w, vnn2_w, out);
}

// round 7
// speedup vs baseline: 1.0732x; 1.0732x over previous
#include <cuda_runtime.h>
#include <math.h>
#include <stdint.h>

#define TLEN  32000
#define BATCH 8
#define RES   32
#define SKIPC 32
#define TT    128

typedef unsigned long long ull;

// ==================== helpers ==============================================
__device__ __forceinline__ uint32_t smem_u32(const void* p) {
    uint32_t a;
    asm("{ .reg .u64 t; cvta.to.shared.u64 t, %1; cvt.u32.u64 %0, t; }" : "=r"(a) : "l"(p));
    return a;
}
__device__ __forceinline__ void sts32(uint32_t a, uint32_t v) {
    asm volatile("st.shared.b32 [%0], %1;" :: "r"(a), "r"(v));
}
__device__ __forceinline__ void ldsm4(uint32_t& r0, uint32_t& r1, uint32_t& r2, uint32_t& r3,
                                      uint32_t addr) {
    asm volatile("ldmatrix.sync.aligned.m8n8.x4.shared.b16 {%0,%1,%2,%3}, [%4];"
                 : "=r"(r0), "=r"(r1), "=r"(r2), "=r"(r3) : "r"(addr));
}
// pack {lo=v0, hi=v1} as bf16x2 (RN)
__device__ __forceinline__ uint32_t pack_bf16x2(float v0, float v1) {
    uint32_t r;
    asm("cvt.rn.bf16x2.f32 %0, %1, %2;" : "=r"(r) : "f"(v1), "f"(v0));
    return r;
}
__device__ __forceinline__ void mma_bf16(float* c,
                                         uint32_t a0, uint32_t a1, uint32_t a2, uint32_t a3,
                                         uint32_t b0, uint32_t b1) {
    asm volatile("mma.sync.aligned.m16n8k16.row.col.f32.bf16.bf16.f32 "
                 "{%0,%1,%2,%3}, {%4,%5,%6,%7}, {%8,%9}, {%0,%1,%2,%3};"
                 : "+f"(c[0]), "+f"(c[1]), "+f"(c[2]), "+f"(c[3])
                 : "r"(a0), "r"(a1), "r"(a2), "r"(a3), "r"(b0), "r"(b1));
}
__device__ __forceinline__ float ftanh(float x) {
    float e = __expf(-2.f * fabsf(x));
    float r = __fdividef(1.f - e, 1.f + e);
    return copysignf(r, x);
}
__device__ __forceinline__ float fsigm(float x) {
    return __fdividef(1.f, 1.f + __expf(-x));
}
// split pair into bf16 hi pack + residual lo pack
__device__ __forceinline__ void split_pair(float v0, float v1, uint32_t& hi, uint32_t& lo) {
    hi = pack_bf16x2(v0, v1);
    float h0 = __uint_as_float((hi & 0xFFFFu) << 16);
    float h1 = __uint_as_float(hi & 0xFFFF0000u);
    lo = pack_bf16x2(v0 - h0, v1 - h1);
}
__device__ __forceinline__ float bfl(uint32_t x) {  // low element
    return __uint_as_float(x << 16);
}
__device__ __forceinline__ float bfh(uint32_t x) {  // high element
    return __uint_as_float(x & 0xFFFF0000u);
}

// ==================== device scratch =======================================
// h as bf16 hi/lo pairs, time-major [b][t][32ch] -> 16 uint32 per (b,t)
__device__ uint32_t g_bh0[BATCH * TLEN * 16];
__device__ uint32_t g_bl0[BATCH * TLEN * 16];
__device__ uint32_t g_bh1[BATCH * TLEN * 16];
__device__ uint32_t g_bl1[BATCH * TLEN * 16];
__device__ float g_skip[BATCH * SKIPC * TLEN];
__device__ float g_ts[BATCH * SKIPC * TLEN];
__device__ float g_p2[BATCH * 16 * TLEN];
__device__ float g_p3[BATCH * 8 * TLEN];
__device__ float g_p4[BATCH * 1 * TLEN];
// pre-split weights, laid out exactly like the smem tiles (incl. padding)
// w1: 64 rows x 52 uint32 (208B row incl pad); w2: 64 rows x 20 uint32 (80B)
__device__ uint32_t g_w1h[10][64 * 52];
__device__ uint32_t g_w1l[10][64 * 52];
__device__ uint32_t g_w2h[10][64 * 20];
__device__ uint32_t g_w2l[10][64 * 20];

// ==================== weight prep: one block per dilation level ============
__global__ __launch_bounds__(TT) void k_wprep(const float* __restrict__ res_w1,
                                              const float* __restrict__ res_w2) {
    int L = blockIdx.x;
    const float* w1 = res_w1 + (size_t)L * 64 * 32 * 3;
    const float* w2 = res_w2 + (size_t)L * 64 * 32;
    int tid = threadIdx.x;
    for (int i = tid; i < 64 * 48; i += TT) {
        int oc = i / 48, pj = i % 48;
        int k0 = 2 * pj;
        int tap = k0 >> 5, ic = k0 & 31;
        float v0 = w1[oc * 96 + ic * 3 + tap];
        float v1 = w1[oc * 96 + (ic + 1) * 3 + tap];
        uint32_t hi, lo;
        split_pair(v0, v1, hi, lo);
        g_w1h[L][oc * 52 + pj] = hi;
        g_w1l[L][oc * 52 + pj] = lo;
    }
    for (int i = tid; i < 64 * 16; i += TT) {
        int oc = i / 16, icp = i % 16;
        float v0 = w2[oc * 32 + 2 * icp];
        float v1 = w2[oc * 32 + 2 * icp + 1];
        uint32_t hi, lo;
        split_pair(v0, v1, hi, lo);
        g_w2h[L][oc * 20 + icp] = hi;
        g_w2l[L][oc * 20 + icp] = lo;
    }
}

// ==================== front conv -> bf16 hi/lo t-major; zero skip ==========
__global__ __launch_bounds__(TT) void k_front(const float* __restrict__ x,
                                              const float* __restrict__ w) {
    int b = blockIdx.y;
    int t = blockIdx.x * TT + threadIdx.x;
    if (t >= TLEN) return;
    const float* xb = x + b * TLEN;
    float x0 = xb[t];
    float x1 = (t >= 1) ? xb[t - 1] : 0.f;
    float x2 = (t >= 2) ? xb[t - 2] : 0.f;
    size_t base = (size_t)(b * TLEN + t) * 16;
#pragma unroll
    for (int p = 0; p < 16; p++) {
        int oc = 2 * p;
        float v0 = fmaf(w[oc * 3 + 0], x2, fmaf(w[oc * 3 + 1], x1, w[oc * 3 + 2] * x0));
        float v1 = fmaf(w[(oc + 1) * 3 + 0], x2,
                   fmaf(w[(oc + 1) * 3 + 1], x1, w[(oc + 1) * 3 + 2] * x0));
        uint32_t hi, lo;
        split_pair(v0, v1, hi, lo);
        g_bh0[base + p] = hi;
        g_bl0[base + p] = lo;
        g_skip[(b * SKIPC + oc) * TLEN + t] = 0.f;
        g_skip[(b * SKIPC + oc + 1) * TLEN + t] = 0.f;
    }
}

// ==================== residual layer =======================================
#define STRA 208   // A/B row stride bytes
#define STRG 80    // G/W2 row stride bytes
#define SO_AH 0
#define SO_AL (SO_AH + 128 * STRA)        // 26624
#define SO_BH (SO_AL + 128 * STRA)        // 53248
#define SO_BL (SO_BH + 64 * STRA)         // 66560
#define SO_GH (SO_BL + 64 * STRA)         // 79872
#define SO_GL (SO_GH + 128 * STRG)        // 90112
#define SO_W2H (SO_GL + 128 * STRG)       // 100352
#define SO_W2L (SO_W2H + 64 * STRG)       // 105472
#define SMEM_LAYER_BYTES (SO_W2L + 64 * STRG)  // 110592

__device__ __forceinline__ void gemm_pass(uint32_t aB, uint32_t bB, int stride,
                                          int nk16, float acc[2][8][4],
                                          int wid, int lid) {
    int lr = lid & 7;
    int aRowOff = lr + ((lid >> 3) & 1) * 8;
    int aKOff = (lid >> 4) * 8;
    int bRowOff = lr + (lid >> 4) * 8;
    int bKOff = ((lid >> 3) & 1) * 8;
    uint32_t aAddr = aB + (uint32_t)((32 * wid + aRowOff) * stride + aKOff * 2);
    uint32_t bAddr0 = bB + (uint32_t)(bRowOff * stride + bKOff * 2);
#pragma unroll
    for (int k = 0; k < nk16; k++) {
        uint32_t ka = (uint32_t)(k * 32);
        uint32_t a0, a1, a2, a3, c0, c1, c2, c3;
        ldsm4(a0, a1, a2, a3, aAddr + ka);
        ldsm4(c0, c1, c2, c3, aAddr + (uint32_t)(16 * stride) + ka);
#pragma unroll
        for (int np = 0; np < 4; np++) {
            uint32_t b0, b1, b2, b3;
            ldsm4(b0, b1, b2, b3, bAddr0 + (uint32_t)(16 * np * stride) + ka);
            mma_bf16(acc[0][2 * np],     a0, a1, a2, a3, b0, b1);
            mma_bf16(acc[0][2 * np + 1], a0, a1, a2, a3, b2, b3);
            mma_bf16(acc[1][2 * np],     c0, c1, c2, c3, b0, b1);
            mma_bf16(acc[1][2 * np + 1], c0, c1, c2, c3, b2, b3);
        }
    }
}

__global__ __launch_bounds__(TT, 2) void k_layer(const uint32_t* __restrict__ hinH,
                                                 const uint32_t* __restrict__ hinL,
                                                 uint32_t* __restrict__ houtH,
                                                 uint32_t* __restrict__ houtL,
                                                 const uint32_t* __restrict__ w1h,
                                                 const uint32_t* __restrict__ w1l,
                                                 const uint32_t* __restrict__ w2h,
                                                 const uint32_t* __restrict__ w2l,
                                                 int d) {
    extern __shared__ __align__(16) char smem[];
    uint32_t sb = smem_u32(smem);
    int tid = threadIdx.x;
    int wid = tid >> 5;
    int lid = tid & 31;
    int qr = lid >> 2;
    int qc = lid & 3;
    int b = blockIdx.y;
    int t0 = blockIdx.x * TT;

    // ---- stage A: pure vectorized copy from pre-split t-major h
    {
        int m = tid;
        int t = t0 + m;
        const uint4 zero4 = make_uint4(0, 0, 0, 0);
#pragma unroll
        for (int tap = 0; tap < 3; tap++) {
            int tt = t - (2 - tap) * d;
            uint32_t dstH = (uint32_t)(SO_AH + m * STRA + tap * 64);
            uint32_t dstL = (uint32_t)(SO_AL + m * STRA + tap * 64);
            if (tt >= 0) {
                const uint4* sH = reinterpret_cast<const uint4*>(hinH + (size_t)(b * TLEN + tt) * 16);
                const uint4* sL = reinterpret_cast<const uint4*>(hinL + (size_t)(b * TLEN + tt) * 16);
#pragma unroll
                for (int j = 0; j < 4; j++) {
                    *reinterpret_cast<uint4*>(smem + dstH + j * 16) = sH[j];
                    *reinterpret_cast<uint4*>(smem + dstL + j * 16) = sL[j];
                }
            } else {
#pragma unroll
                for (int j = 0; j < 4; j++) {
                    *reinterpret_cast<uint4*>(smem + dstH + j * 16) = zero4;
                    *reinterpret_cast<uint4*>(smem + dstL + j * 16) = zero4;
                }
            }
        }
    }
    // ---- weights: linear uint4 copies (source layout == smem layout)
    {
        const uint4* s1h = reinterpret_cast<const uint4*>(w1h);
        const uint4* s1l = reinterpret_cast<const uint4*>(w1l);
        uint4* d1h = reinterpret_cast<uint4*>(smem + SO_BH);
        uint4* d1l = reinterpret_cast<uint4*>(smem + SO_BL);
        for (int i = tid; i < 64 * 13; i += TT) {
            d1h[i] = s1h[i];
            d1l[i] = s1l[i];
        }
        const uint4* s2h = reinterpret_cast<const uint4*>(w2h);
        const uint4* s2l = reinterpret_cast<const uint4*>(w2l);
        uint4* d2h = reinterpret_cast<uint4*>(smem + SO_W2H);
        uint4* d2l = reinterpret_cast<uint4*>(smem + SO_W2L);
        for (int i = tid; i < 64 * 5; i += TT) {
            d2h[i] = s2h[i];
            d2l[i] = s2l[i];
        }
    }
    __syncthreads();

    // ---- conv GEMM: 3 passes
    float acc[2][8][4];
#pragma unroll
    for (int m = 0; m < 2; m++)
#pragma unroll
        for (int n = 0; n < 8; n++)
#pragma unroll
            for (int j = 0; j < 4; j++) acc[m][n][j] = 0.f;

    gemm_pass(sb + SO_AH, sb + SO_BH, STRA, 6, acc, wid, lid);
    gemm_pass(sb + SO_AL, sb + SO_BH, STRA, 6, acc, wid, lid);
    gemm_pass(sb + SO_AH, sb + SO_BL, STRA, 6, acc, wid, lid);

    // ---- gating -> G hi/lo in SMEM
#pragma unroll
    for (int m = 0; m < 2; m++) {
#pragma unroll
        for (int rh = 0; rh < 2; rh++) {
            int row = 32 * wid + 16 * m + qr + 8 * rh;
            uint32_t goff = (uint32_t)(row * STRG + 4 * qc);
#pragma unroll
            for (int n = 0; n < 4; n++) {
                float g0 = ftanh(acc[m][n][2 * rh + 0]) * fsigm(acc[m][n + 4][2 * rh + 0]);
                float g1 = ftanh(acc[m][n][2 * rh + 1]) * fsigm(acc[m][n + 4][2 * rh + 1]);
                uint32_t hi, lo;
                split_pair(g0, g1, hi, lo);
                sts32(sb + SO_GH + goff + (uint32_t)(n * 16), hi);
                sts32(sb + SO_GL + goff + (uint32_t)(n * 16), lo);
            }
        }
    }
    __syncthreads();

    // ---- 1x1 GEMM
    float acc2[2][8][4];
#pragma unroll
    for (int m = 0; m < 2; m++)
#pragma unroll
        for (int n = 0; n < 8; n++)
#pragma unroll
            for (int j = 0; j < 4; j++) acc2[m][n][j] = 0.f;

    gemm_pass(sb + SO_GH, sb + SO_W2H, STRG, 2, acc2, wid, lid);
    gemm_pass(sb + SO_GL, sb + SO_W2H, STRG, 2, acc2, wid, lid);
    gemm_pass(sb + SO_GH, sb + SO_W2L, STRG, 2, acc2, wid, lid);

    // ---- epilogue: residual from A(tap2) + z -> hout hi/lo; skip += z
    float* skb = g_skip + b * SKIPC * TLEN;
#pragma unroll
    for (int m = 0; m < 2; m++) {
#pragma unroll
        for (int rh = 0; rh < 2; rh++) {
            int rowA = 32 * wid + 16 * m + qr + 8 * rh;
            int t = t0 + rowA;
            size_t obase = (size_t)(b * TLEN + t) * 16;
#pragma unroll
            for (int n = 0; n < 4; n++) {
                int c = 8 * n + 2 * qc;
                uint32_t hh = *reinterpret_cast<uint32_t*>(smem + SO_AH + rowA * STRA + (64 + c) * 2);
                uint32_t ll = *reinterpret_cast<uint32_t*>(smem + SO_AL + rowA * STRA + (64 + c) * 2);
                float r0 = bfl(hh) + bfl(ll) + acc2[m][n][2 * rh + 0];
                float r1 = bfh(hh) + bfh(ll) + acc2[m][n][2 * rh + 1];
                uint32_t hi, lo;
                split_pair(r0, r1, hi, lo);
                houtH[obase + (c >> 1)] = hi;
                houtL[obase + (c >> 1)] = lo;
            }
#pragma unroll
            for (int n = 4; n < 8; n++) {
                int c = 8 * (n - 4) + 2 * qc;
                skb[c * TLEN + t]       += acc2[m][n][2 * rh + 0];
                skb[(c + 1) * TLEN + t] += acc2[m][n][2 * rh + 1];
            }
        }
    }
}

// ==================== tanh over skip =======================================
__global__ __launch_bounds__(TT) void k_tanhskip() {
    int b = blockIdx.y;
    int t = blockIdx.x * TT + threadIdx.x;
    if (t >= TLEN) return;
#pragma unroll
    for (int c = 0; c < SKIPC; c++) {
        int idx = (b * SKIPC + c) * TLEN + t;
        g_ts[idx] = ftanh(g_skip[idx]);
    }
}

// ==================== generic causal k=3 conv + tanh =======================
template <int IC, int OC>
__global__ __launch_bounds__(TT) void k_conv3tanh(const float* __restrict__ in,
                                                  float* __restrict__ out,
                                                  const float* __restrict__ w) {
    __shared__ float ws[3][IC][OC];
    int tid = threadIdx.x;
    for (int i = tid; i < OC * IC * 3; i += TT) {
        int oc = i / (IC * 3), r = i % (IC * 3), ic = r / 3, k = r % 3;
        ws[k][ic][oc] = w[i];
    }
    __syncthreads();

    int b = blockIdx.y;
    int t = blockIdx.x * TT + tid;
    if (t >= TLEN) return;
    const float* ib = in + b * IC * TLEN;

    float acc[OC];
#pragma unroll
    for (int o = 0; o < OC; o++) acc[o] = 0.f;
#pragma unroll
    for (int k = 0; k < 3; k++) {
        int tt = t - (2 - k);
        if (tt >= 0) {
#pragma unroll
            for (int ic = 0; ic < IC; ic++) {
                float v = ib[ic * TLEN + tt];
#pragma unroll
                for (int o = 0; o < OC; o++)
                    acc[o] = fmaf(v, ws[k][ic][o], acc[o]);
            }
        }
    }
    float* ob = out + b * OC * TLEN;
#pragma unroll
    for (int o = 0; o < OC; o++)
        ob[o * TLEN + t] = ftanh(acc[o]);
}

// ==================== Volterra head ========================================
__global__ __launch_bounds__(TT) void k_vnn(const float* __restrict__ w1,
                                            const float* __restrict__ w2,
                                            float* __restrict__ out) {
    int b = blockIdx.y;
    int t = blockIdx.x * TT + threadIdx.x;
    if (t >= TLEN) return;
    const float* pb = g_p4 + b * TLEN;

    float pv[16];
#pragma unroll
    for (int k = 0; k < 16; k++) {
        int tt = t - (15 - k);
        pv[k] = (tt >= 0) ? pb[tt] : 0.f;
    }
    float lin = 0.f;
#pragma unroll
    for (int k = 0; k < 16; k++) lin = fmaf(w1[k], pv[k], lin);

    float x2[6];
#pragma unroll
    for (int j = 0; j < 6; j++) {
        float a = 0.f;
#pragma unroll
        for (int k = 0; k < 16; k++) a = fmaf(w2[j * 16 + k], pv[k], a);
        x2[j] = a;
    }
    float quad = x2[0] * x2[3] + x2[1] * x2[4] + x2[2] * x2[5];
    out[b * TLEN + t] = lin + quad;
}

// ==================== host launch ==========================================
extern "C" void kernel_launch(void* const* d_in, const int* in_sizes, int n_in,
                              void* d_out, int out_size) {
    const float* x       = (const float*)d_in[0];
    const float* conv1_w = (const float*)d_in[1];
    const float* res_w1  = (const float*)d_in[2];
    const float* res_w2  = (const float*)d_in[3];
    const float* post2_w = (const float*)d_in[4];
    const float* post3_w = (const float*)d_in[5];
    const float* post4_w = (const float*)d_in[6];
    const float* vnn1_w  = (const float*)d_in[7];
    const float* vnn2_w  = (const float*)d_in[8];
    float* out = (float*)d_out;

    uint32_t *bh0, *bl0, *bh1, *bl1;
    uint32_t *w1h, *w1l, *w2h, *w2l;
    float *tsp, *p2p, *p3p, *p4p;
    cudaGetSymbolAddress((void**)&bh0, g_bh0);
    cudaGetSymbolAddress((void**)&bl0, g_bl0);
    cudaGetSymbolAddress((void**)&bh1, g_bh1);
    cudaGetSymbolAddress((void**)&bl1, g_bl1);
    cudaGetSymbolAddress((void**)&w1h, g_w1h);
    cudaGetSymbolAddress((void**)&w1l, g_w1l);
    cudaGetSymbolAddress((void**)&w2h, g_w2h);
    cudaGetSymbolAddress((void**)&w2l, g_w2l);
    cudaGetSymbolAddress((void**)&tsp, g_ts);
    cudaGetSymbolAddress((void**)&p2p, g_p2);
    cudaGetSymbolAddress((void**)&p3p, g_p3);
    cudaGetSymbolAddress((void**)&p4p, g_p4);

    cudaFuncSetAttribute(k_layer, cudaFuncAttributeMaxDynamicSharedMemorySize,
                         SMEM_LAYER_BYTES);

    dim3 grid(TLEN / TT, BATCH);   // 250 x 8

    k_wprep<<<10, TT>>>(res_w1, res_w2);
    k_front<<<grid, TT>>>(x, conv1_w);

    const uint32_t *hinH = bh0, *hinL = bl0;
    uint32_t *houtH = bh1, *houtL = bl1;
    for (int s = 0; s < 2; s++) {
        for (int i = 0; i < 10; i++) {
            k_layer<<<grid, TT, SMEM_LAYER_BYTES>>>(
                hinH, hinL, houtH, houtL,
                w1h + (size_t)i * 64 * 52, w1l + (size_t)i * 64 * 52,
                w2h + (size_t)i * 64 * 20, w2l + (size_t)i * 64 * 20,
                1 << i);
            const uint32_t* th = houtH; const uint32_t* tl = houtL;
            houtH = (uint32_t*)hinH; houtL = (uint32_t*)hinL;
            hinH = th; hinL = tl;
        }
    }

    k_tanhskip<<<grid, TT>>>();
    k_conv3tanh<32, 16><<<grid, TT>>>(tsp, p2p, post2_w);
    k_conv3tanh<16, 8><<<grid, TT>>>(p2p, p3p, post3_w);
    k_conv3tanh<8, 1><<<grid, TT>>>(p3p, p4p, post4_w);
    k_vnn<<<grid, TT>>>(vnn1_w, vnn2_w, out);
}

// round 8
// speedup vs baseline: 1.2109x; 1.1283x over previous
#include <cuda_runtime.h>
#include <math.h>
#include <stdint.h>

#define TLEN  32000
#define BATCH 8
#define RES   32
#define SKIPC 32
#define TT    128
#define TLT   256   // threads for k_layer (8 warps)

typedef unsigned long long ull;

// ==================== helpers ==============================================
__device__ __forceinline__ uint32_t smem_u32(const void* p) {
    uint32_t a;
    asm("{ .reg .u64 t; cvta.to.shared.u64 t, %1; cvt.u32.u64 %0, t; }" : "=r"(a) : "l"(p));
    return a;
}
__device__ __forceinline__ void sts32(uint32_t a, uint32_t v) {
    asm volatile("st.shared.b32 [%0], %1;" :: "r"(a), "r"(v));
}
__device__ __forceinline__ void ldsm4(uint32_t& r0, uint32_t& r1, uint32_t& r2, uint32_t& r3,
                                      uint32_t addr) {
    asm volatile("ldmatrix.sync.aligned.m8n8.x4.shared.b16 {%0,%1,%2,%3}, [%4];"
                 : "=r"(r0), "=r"(r1), "=r"(r2), "=r"(r3) : "r"(addr));
}
// pack {lo=v0, hi=v1} as bf16x2 (RN)
__device__ __forceinline__ uint32_t pack_bf16x2(float v0, float v1) {
    uint32_t r;
    asm("cvt.rn.bf16x2.f32 %0, %1, %2;" : "=r"(r) : "f"(v1), "f"(v0));
    return r;
}
__device__ __forceinline__ void mma_bf16(float* c,
                                         uint32_t a0, uint32_t a1, uint32_t a2, uint32_t a3,
                                         uint32_t b0, uint32_t b1) {
    asm volatile("mma.sync.aligned.m16n8k16.row.col.f32.bf16.bf16.f32 "
                 "{%0,%1,%2,%3}, {%4,%5,%6,%7}, {%8,%9}, {%0,%1,%2,%3};"
                 : "+f"(c[0]), "+f"(c[1]), "+f"(c[2]), "+f"(c[3])
                 : "r"(a0), "r"(a1), "r"(a2), "r"(a3), "r"(b0), "r"(b1));
}
__device__ __forceinline__ float ftanh(float x) {
    float e = __expf(-2.f * fabsf(x));
    float r = __fdividef(1.f - e, 1.f + e);
    return copysignf(r, x);
}
__device__ __forceinline__ float fsigm(float x) {
    return __fdividef(1.f, 1.f + __expf(-x));
}
// split pair into bf16 hi pack + residual lo pack
__device__ __forceinline__ void split_pair(float v0, float v1, uint32_t& hi, uint32_t& lo) {
    hi = pack_bf16x2(v0, v1);
    float h0 = __uint_as_float((hi & 0xFFFFu) << 16);
    float h1 = __uint_as_float(hi & 0xFFFF0000u);
    lo = pack_bf16x2(v0 - h0, v1 - h1);
}
__device__ __forceinline__ float bfl(uint32_t x) { return __uint_as_float(x << 16); }
__device__ __forceinline__ float bfh(uint32_t x) { return __uint_as_float(x & 0xFFFF0000u); }

// ==================== device scratch =======================================
// h as bf16 hi/lo pairs, time-major [b][t][32ch] -> 16 uint32 per (b,t)
__device__ uint32_t g_bh0[BATCH * TLEN * 16];
__device__ uint32_t g_bl0[BATCH * TLEN * 16];
__device__ uint32_t g_bh1[BATCH * TLEN * 16];
__device__ uint32_t g_bl1[BATCH * TLEN * 16];
__device__ float g_skip[BATCH * TLEN * SKIPC];   // time-major [b][t][32]
__device__ float g_ts[BATCH * SKIPC * TLEN];     // channel-major for post conv
__device__ float g_p2[BATCH * 16 * TLEN];
__device__ float g_p3[BATCH * 8 * TLEN];
__device__ float g_p4[BATCH * 1 * TLEN];
// pre-split weights, laid out exactly like the smem tiles (incl. padding)
__device__ uint32_t g_w1h[10][64 * 52];
__device__ uint32_t g_w1l[10][64 * 52];
__device__ uint32_t g_w2h[10][64 * 20];
__device__ uint32_t g_w2l[10][64 * 20];

// ==================== weight prep ==========================================
__global__ __launch_bounds__(TT) void k_wprep(const float* __restrict__ res_w1,
                                              const float* __restrict__ res_w2) {
    int L = blockIdx.x;
    const float* w1 = res_w1 + (size_t)L * 64 * 32 * 3;
    const float* w2 = res_w2 + (size_t)L * 64 * 32;
    int tid = threadIdx.x;
    for (int i = tid; i < 64 * 48; i += TT) {
        int oc = i / 48, pj = i % 48;
        int k0 = 2 * pj;
        int tap = k0 >> 5, ic = k0 & 31;
        float v0 = w1[oc * 96 + ic * 3 + tap];
        float v1 = w1[oc * 96 + (ic + 1) * 3 + tap];
        uint32_t hi, lo;
        split_pair(v0, v1, hi, lo);
        g_w1h[L][oc * 52 + pj] = hi;
        g_w1l[L][oc * 52 + pj] = lo;
    }
    for (int i = tid; i < 64 * 16; i += TT) {
        int oc = i / 16, icp = i % 16;
        float v0 = w2[oc * 32 + 2 * icp];
        float v1 = w2[oc * 32 + 2 * icp + 1];
        uint32_t hi, lo;
        split_pair(v0, v1, hi, lo);
        g_w2h[L][oc * 20 + icp] = hi;
        g_w2l[L][oc * 20 + icp] = lo;
    }
}

// ==================== front conv -> bf16 hi/lo t-major; zero skip ==========
__global__ __launch_bounds__(TT) void k_front(const float* __restrict__ x,
                                              const float* __restrict__ w) {
    int b = blockIdx.y;
    int t = blockIdx.x * TT + threadIdx.x;
    if (t >= TLEN) return;
    const float* xb = x + b * TLEN;
    float x0 = xb[t];
    float x1 = (t >= 1) ? xb[t - 1] : 0.f;
    float x2 = (t >= 2) ? xb[t - 2] : 0.f;
    size_t base = (size_t)(b * TLEN + t) * 16;
    float* sk = g_skip + (size_t)(b * TLEN + t) * 32;
#pragma unroll
    for (int p = 0; p < 16; p++) {
        int oc = 2 * p;
        float v0 = fmaf(w[oc * 3 + 0], x2, fmaf(w[oc * 3 + 1], x1, w[oc * 3 + 2] * x0));
        float v1 = fmaf(w[(oc + 1) * 3 + 0], x2,
                   fmaf(w[(oc + 1) * 3 + 1], x1, w[(oc + 1) * 3 + 2] * x0));
        uint32_t hi, lo;
        split_pair(v0, v1, hi, lo);
        g_bh0[base + p] = hi;
        g_bl0[base + p] = lo;
        sk[oc] = 0.f;
        sk[oc + 1] = 0.f;
    }
}

// ==================== residual layer =======================================
#define STRA 208   // A/B row stride bytes
#define STRG 80    // G/W2 row stride bytes
#define SO_AH 0
#define SO_AL (SO_AH + 128 * STRA)
#define SO_BH (SO_AL + 128 * STRA)
#define SO_BL (SO_BH + 64 * STRA)
#define SO_GH (SO_BL + 64 * STRA)
#define SO_GL (SO_GH + 128 * STRG)
#define SO_W2H (SO_GL + 128 * STRG)
#define SO_W2L (SO_W2H + 64 * STRG)
#define SMEM_LAYER_BYTES (SO_W2L + 64 * STRG)  // 110592

// warp w handles rows [16w, 16w+16); acc[n][4] over 8 n8-tiles
__device__ __forceinline__ void gemm_pass(uint32_t aB, uint32_t bB, int stride,
                                          int nk16, float acc[8][4],
                                          int wid, int lid) {
    int lr = lid & 7;
    int aRowOff = lr + ((lid >> 3) & 1) * 8;
    int aKOff = (lid >> 4) * 8;
    int bRowOff = lr + (lid >> 4) * 8;
    int bKOff = ((lid >> 3) & 1) * 8;
    uint32_t aAddr = aB + (uint32_t)((16 * wid + aRowOff) * stride + aKOff * 2);
    uint32_t bAddr0 = bB + (uint32_t)(bRowOff * stride + bKOff * 2);
#pragma unroll
    for (int k = 0; k < nk16; k++) {
        uint32_t ka = (uint32_t)(k * 32);
        uint32_t a0, a1, a2, a3;
        ldsm4(a0, a1, a2, a3, aAddr + ka);
#pragma unroll
        for (int np = 0; np < 4; np++) {
            uint32_t b0, b1, b2, b3;
            ldsm4(b0, b1, b2, b3, bAddr0 + (uint32_t)(16 * np * stride) + ka);
            mma_bf16(acc[2 * np],     a0, a1, a2, a3, b0, b1);
            mma_bf16(acc[2 * np + 1], a0, a1, a2, a3, b2, b3);
        }
    }
}

__global__ __launch_bounds__(TLT, 2) void k_layer(const uint32_t* __restrict__ hinH,
                                                  const uint32_t* __restrict__ hinL,
                                                  uint32_t* __restrict__ houtH,
                                                  uint32_t* __restrict__ houtL,
                                                  const uint32_t* __restrict__ w1h,
                                                  const uint32_t* __restrict__ w1l,
                                                  const uint32_t* __restrict__ w2h,
                                                  const uint32_t* __restrict__ w2l,
                                                  int d) {
    extern __shared__ __align__(16) char smem[];
    uint32_t sb = smem_u32(smem);
    int tid = threadIdx.x;
    int wid = tid >> 5;
    int lid = tid & 31;
    int qr = lid >> 2;
    int qc = lid & 3;
    int b = blockIdx.y;
    int t0 = blockIdx.x * 128;

    // ---- stage A: vectorized copy; 768 copy-units of 64B (row,tap,arr)
    {
        const uint4 zero4 = make_uint4(0, 0, 0, 0);
#pragma unroll
        for (int u = 0; u < 3; u++) {
            int idx = tid + u * TLT;   // 0..767
            int m = idx / 6;
            int j = idx % 6;
            int tap = j >> 1;
            int arr = j & 1;
            int tt = t0 + m - (2 - tap) * d;
            uint32_t dst = (uint32_t)((arr ? SO_AL : SO_AH) + m * STRA + tap * 64);
            if (tt >= 0) {
                const uint32_t* src = (arr ? hinL : hinH) + (size_t)(b * TLEN + tt) * 16;
                const uint4* s4 = reinterpret_cast<const uint4*>(src);
#pragma unroll
                for (int q = 0; q < 4; q++)
                    *reinterpret_cast<uint4*>(smem + dst + q * 16) = s4[q];
            } else {
#pragma unroll
                for (int q = 0; q < 4; q++)
                    *reinterpret_cast<uint4*>(smem + dst + q * 16) = zero4;
            }
        }
    }
    // ---- weights: linear uint4 copies
    {
        const uint4* s1h = reinterpret_cast<const uint4*>(w1h);
        const uint4* s1l = reinterpret_cast<const uint4*>(w1l);
        uint4* d1h = reinterpret_cast<uint4*>(smem + SO_BH);
        uint4* d1l = reinterpret_cast<uint4*>(smem + SO_BL);
        for (int i = tid; i < 64 * 13; i += TLT) {
            d1h[i] = s1h[i];
            d1l[i] = s1l[i];
        }
        const uint4* s2h = reinterpret_cast<const uint4*>(w2h);
        const uint4* s2l = reinterpret_cast<const uint4*>(w2l);
        uint4* d2h = reinterpret_cast<uint4*>(smem + SO_W2H);
        uint4* d2l = reinterpret_cast<uint4*>(smem + SO_W2L);
        for (int i = tid; i < 64 * 5; i += TLT) {
            d2h[i] = s2h[i];
            d2l[i] = s2l[i];
        }
    }
    __syncthreads();

    // ---- conv GEMM: 3 passes
    float acc[8][4];
#pragma unroll
    for (int n = 0; n < 8; n++)
#pragma unroll
        for (int j = 0; j < 4; j++) acc[n][j] = 0.f;

    gemm_pass(sb + SO_AH, sb + SO_BH, STRA, 6, acc, wid, lid);
    gemm_pass(sb + SO_AL, sb + SO_BH, STRA, 6, acc, wid, lid);
    gemm_pass(sb + SO_AH, sb + SO_BL, STRA, 6, acc, wid, lid);

    // ---- gating -> G hi/lo in SMEM (warp rows 16w..16w+15)
#pragma unroll
    for (int rh = 0; rh < 2; rh++) {
        int row = 16 * wid + qr + 8 * rh;
        uint32_t goff = (uint32_t)(row * STRG + 4 * qc);
#pragma unroll
        for (int n = 0; n < 4; n++) {
            float g0 = ftanh(acc[n][2 * rh + 0]) * fsigm(acc[n + 4][2 * rh + 0]);
            float g1 = ftanh(acc[n][2 * rh + 1]) * fsigm(acc[n + 4][2 * rh + 1]);
            uint32_t hi, lo;
            split_pair(g0, g1, hi, lo);
            sts32(sb + SO_GH + goff + (uint32_t)(n * 16), hi);
            sts32(sb + SO_GL + goff + (uint32_t)(n * 16), lo);
        }
    }
    __syncthreads();

    // ---- 1x1 GEMM
    float acc2[8][4];
#pragma unroll
    for (int n = 0; n < 8; n++)
#pragma unroll
        for (int j = 0; j < 4; j++) acc2[n][j] = 0.f;

    gemm_pass(sb + SO_GH, sb + SO_W2H, STRG, 2, acc2, wid, lid);
    gemm_pass(sb + SO_GL, sb + SO_W2H, STRG, 2, acc2, wid, lid);
    gemm_pass(sb + SO_GH, sb + SO_W2L, STRG, 2, acc2, wid, lid);

    // ---- epilogue: residual from A(tap2) + z -> hout; skip (t-major) += z
#pragma unroll
    for (int rh = 0; rh < 2; rh++) {
        int rowA = 16 * wid + qr + 8 * rh;
        int t = t0 + rowA;
        size_t obase = (size_t)(b * TLEN + t) * 16;
        float2* sk = reinterpret_cast<float2*>(g_skip + (size_t)(b * TLEN + t) * 32);
#pragma unroll
        for (int n = 0; n < 4; n++) {
            int c = 8 * n + 2 * qc;
            uint32_t hh = *reinterpret_cast<uint32_t*>(smem + SO_AH + rowA * STRA + (64 + c) * 2);
            uint32_t ll = *reinterpret_cast<uint32_t*>(smem + SO_AL + rowA * STRA + (64 + c) * 2);
            float r0 = bfl(hh) + bfl(ll) + acc2[n][2 * rh + 0];
            float r1 = bfh(hh) + bfh(ll) + acc2[n][2 * rh + 1];
            uint32_t hi, lo;
            split_pair(r0, r1, hi, lo);
            houtH[obase + (c >> 1)] = hi;
            houtL[obase + (c >> 1)] = lo;
        }
#pragma unroll
        for (int n = 4; n < 8; n++) {
            int c = 8 * (n - 4) + 2 * qc;
            float2 v = sk[c >> 1];
            v.x += acc2[n][2 * rh + 0];
            v.y += acc2[n][2 * rh + 1];
            sk[c >> 1] = v;
        }
    }
}

// ==================== tanh over skip (t-major -> channel-major) ============
__global__ __launch_bounds__(TT) void k_tanhskip() {
    int b = blockIdx.y;
    int t = blockIdx.x * TT + threadIdx.x;
    if (t >= TLEN) return;
    const float* sk = g_skip + (size_t)(b * TLEN + t) * 32;
#pragma unroll
    for (int c = 0; c < SKIPC; c++)
        g_ts[(b * SKIPC + c) * TLEN + t] = ftanh(sk[c]);
}

// ==================== generic causal k=3 conv + tanh =======================
template <int IC, int OC>
__global__ __launch_bounds__(TT) void k_conv3tanh(const float* __restrict__ in,
                                                  float* __restrict__ out,
                                                  const float* __restrict__ w) {
    __shared__ float ws[3][IC][OC];
    int tid = threadIdx.x;
    for (int i = tid; i < OC * IC * 3; i += TT) {
        int oc = i / (IC * 3), r = i % (IC * 3), ic = r / 3, k = r % 3;
        ws[k][ic][oc] = w[i];
    }
    __syncthreads();

    int b = blockIdx.y;
    int t = blockIdx.x * TT + tid;
    if (t >= TLEN) return;
    const float* ib = in + b * IC * TLEN;

    float acc[OC];
#pragma unroll
    for (int o = 0; o < OC; o++) acc[o] = 0.f;
#pragma unroll
    for (int k = 0; k < 3; k++) {
        int tt = t - (2 - k);
        if (tt >= 0) {
#pragma unroll
            for (int ic = 0; ic < IC; ic++) {
                float v = ib[ic * TLEN + tt];
#pragma unroll
                for (int o = 0; o < OC; o++)
                    acc[o] = fmaf(v, ws[k][ic][o], acc[o]);
            }
        }
    }
    float* ob = out + b * OC * TLEN;
#pragma unroll
    for (int o = 0; o < OC; o++)
        ob[o * TLEN + t] = ftanh(acc[o]);
}

// ==================== Volterra head ========================================
__global__ __launch_bounds__(TT) void k_vnn(const float* __restrict__ w1,
                                            const float* __restrict__ w2,
                                            float* __restrict__ out) {
    int b = blockIdx.y;
    int t = blockIdx.x * TT + threadIdx.x;
    if (t >= TLEN) return;
    const float* pb = g_p4 + b * TLEN;

    float pv[16];
#pragma unroll
    for (int k = 0; k < 16; k++) {
        int tt = t - (15 - k);
        pv[k] = (tt >= 0) ? pb[tt] : 0.f;
    }
    float lin = 0.f;
#pragma unroll
    for (int k = 0; k < 16; k++) lin = fmaf(w1[k], pv[k], lin);

    float x2[6];
#pragma unroll
    for (int j = 0; j < 6; j++) {
        float a = 0.f;
#pragma unroll
        for (int k = 0; k < 16; k++) a = fmaf(w2[j * 16 + k], pv[k], a);
        x2[j] = a;
    }
    float quad = x2[0] * x2[3] + x2[1] * x2[4] + x2[2] * x2[5];
    out[b * TLEN + t] = lin + quad;
}

// ==================== host launch ==========================================
extern "C" void kernel_launch(void* const* d_in, const int* in_sizes, int n_in,
                              void* d_out, int out_size) {
    const float* x       = (const float*)d_in[0];
    const float* conv1_w = (const float*)d_in[1];
    const float* res_w1  = (const float*)d_in[2];
    const float* res_w2  = (const float*)d_in[3];
    const float* post2_w = (const float*)d_in[4];
    const float* post3_w = (const float*)d_in[5];
    const float* post4_w = (const float*)d_in[6];
    const float* vnn1_w  = (const float*)d_in[7];
    const float* vnn2_w  = (const float*)d_in[8];
    float* out = (float*)d_out;

    uint32_t *bh0, *bl0, *bh1, *bl1;
    uint32_t *w1h, *w1l, *w2h, *w2l;
    float *tsp, *p2p, *p3p, *p4p;
    cudaGetSymbolAddress((void**)&bh0, g_bh0);
    cudaGetSymbolAddress((void**)&bl0, g_bl0);
    cudaGetSymbolAddress((void**)&bh1, g_bh1);
    cudaGetSymbolAddress((void**)&bl1, g_bl1);
    cudaGetSymbolAddress((void**)&w1h, g_w1h);
    cudaGetSymbolAddress((void**)&w1l, g_w1l);
    cudaGetSymbolAddress((void**)&w2h, g_w2h);
    cudaGetSymbolAddress((void**)&w2l, g_w2l);
    cudaGetSymbolAddress((void**)&tsp, g_ts);
    cudaGetSymbolAddress((void**)&p2p, g_p2);
    cudaGetSymbolAddress((void**)&p3p, g_p3);
    cudaGetSymbolAddress((void**)&p4p, g_p4);

    cudaFuncSetAttribute(k_layer, cudaFuncAttributeMaxDynamicSharedMemorySize,
                         SMEM_LAYER_BYTES);

    dim3 grid(TLEN / 128, BATCH);   // 250 x 8

    k_wprep<<<10, TT>>>(res_w1, res_w2);
    k_front<<<grid, TT>>>(x, conv1_w);

    const uint32_t *hinH = bh0, *hinL = bl0;
    uint32_t *houtH = bh1, *houtL = bl1;
    for (int s = 0; s < 2; s++) {
        for (int i = 0; i < 10; i++) {
            k_layer<<<grid, TLT, SMEM_LAYER_BYTES>>>(
                hinH, hinL, houtH, houtL,
                w1h + (size_t)i * 64 * 52, w1l + (size_t)i * 64 * 52,
                w2h + (size_t)i * 64 * 20, w2l + (size_t)i * 64 * 20,
                1 << i);
            const uint32_t* th = houtH; const uint32_t* tl = houtL;
            houtH = (uint32_t*)hinH; houtL = (uint32_t*)hinL;
            hinH = th; hinL = tl;
        }
    }

    k_tanhskip<<<grid, TT>>>();
    k_conv3tanh<32, 16><<<grid, TT>>>(tsp, p2p, post2_w);
    k_conv3tanh<16, 8><<<grid, TT>>>(p2p, p3p, post3_w);
    k_conv3tanh<8, 1><<<grid, TT>>>(p3p, p4p, post4_w);
    k_vnn<<<grid, TT>>>(vnn1_w, vnn2_w, out);
}

// round 9
// speedup vs baseline: 1.2631x; 1.0431x over previous
#include <cuda_runtime.h>
#include <math.h>
#include <stdint.h>

#define TLEN  32000
#define BATCH 8
#define RES   32
#define SKIPC 32
#define TT    128
#define TLT   256   // threads for k_layer (8 warps)

typedef unsigned long long ull;

// ==================== helpers ==============================================
__device__ __forceinline__ uint32_t smem_u32(const void* p) {
    uint32_t a;
    asm("{ .reg .u64 t; cvta.to.shared.u64 t, %1; cvt.u32.u64 %0, t; }" : "=r"(a) : "l"(p));
    return a;
}
__device__ __forceinline__ void sts32(uint32_t a, uint32_t v) {
    asm volatile("st.shared.b32 [%0], %1;" :: "r"(a), "r"(v));
}
__device__ __forceinline__ void ldsm4(uint32_t& r0, uint32_t& r1, uint32_t& r2, uint32_t& r3,
                                      uint32_t addr) {
    asm volatile("ldmatrix.sync.aligned.m8n8.x4.shared.b16 {%0,%1,%2,%3}, [%4];"
                 : "=r"(r0), "=r"(r1), "=r"(r2), "=r"(r3) : "r"(addr));
}
// pack {lo=v0, hi=v1} as bf16x2 (RN)
__device__ __forceinline__ uint32_t pack_bf16x2(float v0, float v1) {
    uint32_t r;
    asm("cvt.rn.bf16x2.f32 %0, %1, %2;" : "=r"(r) : "f"(v1), "f"(v0));
    return r;
}
__device__ __forceinline__ void mma_bf16(float* c,
                                         uint32_t a0, uint32_t a1, uint32_t a2, uint32_t a3,
                                         uint32_t b0, uint32_t b1) {
    asm volatile("mma.sync.aligned.m16n8k16.row.col.f32.bf16.bf16.f32 "
                 "{%0,%1,%2,%3}, {%4,%5,%6,%7}, {%8,%9}, {%0,%1,%2,%3};"
                 : "+f"(c[0]), "+f"(c[1]), "+f"(c[2]), "+f"(c[3])
                 : "r"(a0), "r"(a1), "r"(a2), "r"(a3), "r"(b0), "r"(b1));
}
__device__ __forceinline__ float ftanh(float x) {
    float e = __expf(-2.f * fabsf(x));
    float r = __fdividef(1.f - e, 1.f + e);
    return copysignf(r, x);
}
__device__ __forceinline__ float fsigm(float x) {
    return __fdividef(1.f, 1.f + __expf(-x));
}
// split pair into bf16 hi pack + residual lo pack
__device__ __forceinline__ void split_pair(float v0, float v1, uint32_t& hi, uint32_t& lo) {
    hi = pack_bf16x2(v0, v1);
    float h0 = __uint_as_float((hi & 0xFFFFu) << 16);
    float h1 = __uint_as_float(hi & 0xFFFF0000u);
    lo = pack_bf16x2(v0 - h0, v1 - h1);
}
__device__ __forceinline__ float bfl(uint32_t x) { return __uint_as_float(x << 16); }
__device__ __forceinline__ float bfh(uint32_t x) { return __uint_as_float(x & 0xFFFF0000u); }

// ==================== device scratch =======================================
__device__ uint32_t g_bh0[BATCH * TLEN * 16];
__device__ uint32_t g_bl0[BATCH * TLEN * 16];
__device__ uint32_t g_bh1[BATCH * TLEN * 16];
__device__ uint32_t g_bl1[BATCH * TLEN * 16];
__device__ float g_skip[BATCH * TLEN * SKIPC];   // time-major [b][t][32]
__device__ float g_ts[BATCH * SKIPC * TLEN];     // channel-major for post conv
__device__ float g_p2[BATCH * 16 * TLEN];
__device__ float g_p3[BATCH * 8 * TLEN];
__device__ float g_p4[BATCH * 1 * TLEN];
__device__ uint32_t g_w1h[10][64 * 52];
__device__ uint32_t g_w1l[10][64 * 52];
__device__ uint32_t g_w2h[10][64 * 20];
__device__ uint32_t g_w2l[10][64 * 20];

// ==================== weight prep ==========================================
__global__ __launch_bounds__(TT) void k_wprep(const float* __restrict__ res_w1,
                                              const float* __restrict__ res_w2) {
    int L = blockIdx.x;
    const float* w1 = res_w1 + (size_t)L * 64 * 32 * 3;
    const float* w2 = res_w2 + (size_t)L * 64 * 32;
    int tid = threadIdx.x;
    for (int i = tid; i < 64 * 48; i += TT) {
        int oc = i / 48, pj = i % 48;
        int k0 = 2 * pj;
        int tap = k0 >> 5, ic = k0 & 31;
        float v0 = w1[oc * 96 + ic * 3 + tap];
        float v1 = w1[oc * 96 + (ic + 1) * 3 + tap];
        uint32_t hi, lo;
        split_pair(v0, v1, hi, lo);
        g_w1h[L][oc * 52 + pj] = hi;
        g_w1l[L][oc * 52 + pj] = lo;
    }
    for (int i = tid; i < 64 * 16; i += TT) {
        int oc = i / 16, icp = i % 16;
        float v0 = w2[oc * 32 + 2 * icp];
        float v1 = w2[oc * 32 + 2 * icp + 1];
        uint32_t hi, lo;
        split_pair(v0, v1, hi, lo);
        g_w2h[L][oc * 20 + icp] = hi;
        g_w2l[L][oc * 20 + icp] = lo;
    }
}

// ==================== front conv -> bf16 hi/lo t-major; zero skip ==========
__global__ __launch_bounds__(TT) void k_front(const float* __restrict__ x,
                                              const float* __restrict__ w) {
    int b = blockIdx.y;
    int t = blockIdx.x * TT + threadIdx.x;
    if (t >= TLEN) return;
    const float* xb = x + b * TLEN;
    float x0 = xb[t];
    float x1 = (t >= 1) ? xb[t - 1] : 0.f;
    float x2 = (t >= 2) ? xb[t - 2] : 0.f;
    size_t base = (size_t)(b * TLEN + t) * 16;
    float* sk = g_skip + (size_t)(b * TLEN + t) * 32;
#pragma unroll
    for (int p = 0; p < 16; p++) {
        int oc = 2 * p;
        float v0 = fmaf(w[oc * 3 + 0], x2, fmaf(w[oc * 3 + 1], x1, w[oc * 3 + 2] * x0));
        float v1 = fmaf(w[(oc + 1) * 3 + 0], x2,
                   fmaf(w[(oc + 1) * 3 + 1], x1, w[(oc + 1) * 3 + 2] * x0));
        uint32_t hi, lo;
        split_pair(v0, v1, hi, lo);
        g_bh0[base + p] = hi;
        g_bl0[base + p] = lo;
        sk[oc] = 0.f;
        sk[oc + 1] = 0.f;
    }
}

// ==================== residual layer =======================================
#define STRA 208
#define STRG 80
#define SO_AH 0
#define SO_AL (SO_AH + 128 * STRA)
#define SO_BH (SO_AL + 128 * STRA)
#define SO_BL (SO_BH + 64 * STRA)
#define SO_GH (SO_BL + 64 * STRA)
#define SO_GL (SO_GH + 128 * STRG)
#define SO_W2H (SO_GL + 128 * STRG)
#define SO_W2L (SO_W2H + 64 * STRG)
#define SMEM_LAYER_BYTES (SO_W2L + 64 * STRG)  // 110592

// fused 3-combo GEMM: acc += AH·BH^T + AL·BH^T + AH·BL^T over K=nk16*16
// warp w owns rows [16w, 16w+16); loads each fragment once per k-step
__device__ __forceinline__ void gemm_fused(uint32_t aHB, uint32_t aLB,
                                           uint32_t bHB, uint32_t bLB,
                                           int stride, int nk16, float acc[8][4],
                                           int wid, int lid) {
    int lr = lid & 7;
    int aRowOff = lr + ((lid >> 3) & 1) * 8;
    int aKOff = (lid >> 4) * 8;
    int bRowOff = lr + (lid >> 4) * 8;
    int bKOff = ((lid >> 3) & 1) * 8;
    uint32_t aH = aHB + (uint32_t)((16 * wid + aRowOff) * stride + aKOff * 2);
    uint32_t aL = aLB + (uint32_t)((16 * wid + aRowOff) * stride + aKOff * 2);
    uint32_t bH0 = bHB + (uint32_t)(bRowOff * stride + bKOff * 2);
    uint32_t bL0 = bLB + (uint32_t)(bRowOff * stride + bKOff * 2);
#pragma unroll
    for (int k = 0; k < nk16; k++) {
        uint32_t ka = (uint32_t)(k * 32);
        uint32_t ah0, ah1, ah2, ah3, al0, al1, al2, al3;
        ldsm4(ah0, ah1, ah2, ah3, aH + ka);
        ldsm4(al0, al1, al2, al3, aL + ka);
#pragma unroll
        for (int np = 0; np < 4; np++) {
            uint32_t off = (uint32_t)(16 * np * stride) + ka;
            uint32_t bh0, bh1, bh2, bh3, bl0, bl1, bl2, bl3;
            ldsm4(bh0, bh1, bh2, bh3, bH0 + off);
            ldsm4(bl0, bl1, bl2, bl3, bL0 + off);
            mma_bf16(acc[2 * np],     ah0, ah1, ah2, ah3, bh0, bh1);
            mma_bf16(acc[2 * np + 1], ah0, ah1, ah2, ah3, bh2, bh3);
            mma_bf16(acc[2 * np],     al0, al1, al2, al3, bh0, bh1);
            mma_bf16(acc[2 * np + 1], al0, al1, al2, al3, bh2, bh3);
            mma_bf16(acc[2 * np],     ah0, ah1, ah2, ah3, bl0, bl1);
            mma_bf16(acc[2 * np + 1], ah0, ah1, ah2, ah3, bl2, bl3);
        }
    }
}

__global__ __launch_bounds__(TLT, 2) void k_layer(const uint32_t* __restrict__ hinH,
                                                  const uint32_t* __restrict__ hinL,
                                                  uint32_t* __restrict__ houtH,
                                                  uint32_t* __restrict__ houtL,
                                                  const uint32_t* __restrict__ w1h,
                                                  const uint32_t* __restrict__ w1l,
                                                  const uint32_t* __restrict__ w2h,
                                                  const uint32_t* __restrict__ w2l,
                                                  int d) {
    extern __shared__ __align__(16) char smem[];
    uint32_t sb = smem_u32(smem);
    int tid = threadIdx.x;
    int wid = tid >> 5;
    int lid = tid & 31;
    int qr = lid >> 2;
    int qc = lid & 3;
    int b = blockIdx.y;
    int t0 = blockIdx.x * 128;

    // ---- stage A: vectorized copy; 768 copy-units of 64B (row,tap,arr)
    {
        const uint4 zero4 = make_uint4(0, 0, 0, 0);
#pragma unroll
        for (int u = 0; u < 3; u++) {
            int idx = tid + u * TLT;
            int m = idx / 6;
            int j = idx % 6;
            int tap = j >> 1;
            int arr = j & 1;
            int tt = t0 + m - (2 - tap) * d;
            uint32_t dst = (uint32_t)((arr ? SO_AL : SO_AH) + m * STRA + tap * 64);
            if (tt >= 0) {
                const uint32_t* src = (arr ? hinL : hinH) + (size_t)(b * TLEN + tt) * 16;
                const uint4* s4 = reinterpret_cast<const uint4*>(src);
#pragma unroll
                for (int q = 0; q < 4; q++)
                    *reinterpret_cast<uint4*>(smem + dst + q * 16) = s4[q];
            } else {
#pragma unroll
                for (int q = 0; q < 4; q++)
                    *reinterpret_cast<uint4*>(smem + dst + q * 16) = zero4;
            }
        }
    }
    // ---- weights: linear uint4 copies
    {
        const uint4* s1h = reinterpret_cast<const uint4*>(w1h);
        const uint4* s1l = reinterpret_cast<const uint4*>(w1l);
        uint4* d1h = reinterpret_cast<uint4*>(smem + SO_BH);
        uint4* d1l = reinterpret_cast<uint4*>(smem + SO_BL);
        for (int i = tid; i < 64 * 13; i += TLT) {
            d1h[i] = s1h[i];
            d1l[i] = s1l[i];
        }
        const uint4* s2h = reinterpret_cast<const uint4*>(w2h);
        const uint4* s2l = reinterpret_cast<const uint4*>(w2l);
        uint4* d2h = reinterpret_cast<uint4*>(smem + SO_W2H);
        uint4* d2l = reinterpret_cast<uint4*>(smem + SO_W2L);
        for (int i = tid; i < 64 * 5; i += TLT) {
            d2h[i] = s2h[i];
            d2l[i] = s2l[i];
        }
    }
    __syncthreads();

    // ---- conv GEMM: fused 3-combo
    float acc[8][4];
#pragma unroll
    for (int n = 0; n < 8; n++)
#pragma unroll
        for (int j = 0; j < 4; j++) acc[n][j] = 0.f;

    gemm_fused(sb + SO_AH, sb + SO_AL, sb + SO_BH, sb + SO_BL, STRA, 6, acc, wid, lid);

    // ---- gating -> G hi/lo in SMEM
#pragma unroll
    for (int rh = 0; rh < 2; rh++) {
        int row = 16 * wid + qr + 8 * rh;
        uint32_t goff = (uint32_t)(row * STRG + 4 * qc);
#pragma unroll
        for (int n = 0; n < 4; n++) {
            float g0 = ftanh(acc[n][2 * rh + 0]) * fsigm(acc[n + 4][2 * rh + 0]);
            float g1 = ftanh(acc[n][2 * rh + 1]) * fsigm(acc[n + 4][2 * rh + 1]);
            uint32_t hi, lo;
            split_pair(g0, g1, hi, lo);
            sts32(sb + SO_GH + goff + (uint32_t)(n * 16), hi);
            sts32(sb + SO_GL + goff + (uint32_t)(n * 16), lo);
        }
    }
    __syncthreads();

    // ---- 1x1 GEMM: fused 3-combo
    float acc2[8][4];
#pragma unroll
    for (int n = 0; n < 8; n++)
#pragma unroll
        for (int j = 0; j < 4; j++) acc2[n][j] = 0.f;

    gemm_fused(sb + SO_GH, sb + SO_GL, sb + SO_W2H, sb + SO_W2L, STRG, 2, acc2, wid, lid);

    // ---- epilogue: residual from A(tap2) + z -> hout; skip (t-major) += z
#pragma unroll
    for (int rh = 0; rh < 2; rh++) {
        int rowA = 16 * wid + qr + 8 * rh;
        int t = t0 + rowA;
        size_t obase = (size_t)(b * TLEN + t) * 16;
        float2* sk = reinterpret_cast<float2*>(g_skip + (size_t)(b * TLEN + t) * 32);
#pragma unroll
        for (int n = 0; n < 4; n++) {
            int c = 8 * n + 2 * qc;
            uint32_t hh = *reinterpret_cast<uint32_t*>(smem + SO_AH + rowA * STRA + (64 + c) * 2);
            uint32_t ll = *reinterpret_cast<uint32_t*>(smem + SO_AL + rowA * STRA + (64 + c) * 2);
            float r0 = bfl(hh) + bfl(ll) + acc2[n][2 * rh + 0];
            float r1 = bfh(hh) + bfh(ll) + acc2[n][2 * rh + 1];
            uint32_t hi, lo;
            split_pair(r0, r1, hi, lo);
            houtH[obase + (c >> 1)] = hi;
            houtL[obase + (c >> 1)] = lo;
        }
#pragma unroll
        for (int n = 4; n < 8; n++) {
            int c = 8 * (n - 4) + 2 * qc;
            float2 v = sk[c >> 1];
            v.x += acc2[n][2 * rh + 0];
            v.y += acc2[n][2 * rh + 1];
            sk[c >> 1] = v;
        }
    }
}

// ==================== tanh over skip (t-major -> channel-major) ============
__global__ __launch_bounds__(TT) void k_tanhskip() {
    int b = blockIdx.y;
    int t = blockIdx.x * TT + threadIdx.x;
    if (t >= TLEN) return;
    const float* sk = g_skip + (size_t)(b * TLEN + t) * 32;
#pragma unroll
    for (int c = 0; c < SKIPC; c++)
        g_ts[(b * SKIPC + c) * TLEN + t] = ftanh(sk[c]);
}

// ==================== generic causal k=3 conv + tanh =======================
template <int IC, int OC>
__global__ __launch_bounds__(TT) void k_conv3tanh(const float* __restrict__ in,
                                                  float* __restrict__ out,
                                                  const float* __restrict__ w) {
    __shared__ float ws[3][IC][OC];
    int tid = threadIdx.x;
    for (int i = tid; i < OC * IC * 3; i += TT) {
        int oc = i / (IC * 3), r = i % (IC * 3), ic = r / 3, k = r % 3;
        ws[k][ic][oc] = w[i];
    }
    __syncthreads();

    int b = blockIdx.y;
    int t = blockIdx.x * TT + tid;
    if (t >= TLEN) return;
    const float* ib = in + b * IC * TLEN;

    float acc[OC];
#pragma unroll
    for (int o = 0; o < OC; o++) acc[o] = 0.f;
#pragma unroll
    for (int k = 0; k < 3; k++) {
        int tt = t - (2 - k);
        if (tt >= 0) {
#pragma unroll
            for (int ic = 0; ic < IC; ic++) {
                float v = ib[ic * TLEN + tt];
#pragma unroll
                for (int o = 0; o < OC; o++)
                    acc[o] = fmaf(v, ws[k][ic][o], acc[o]);
            }
        }
    }
    float* ob = out + b * OC * TLEN;
#pragma unroll
    for (int o = 0; o < OC; o++)
        ob[o * TLEN + t] = ftanh(acc[o]);
}

// ==================== Volterra head ========================================
__global__ __launch_bounds__(TT) void k_vnn(const float* __restrict__ w1,
                                            const float* __restrict__ w2,
                                            float* __restrict__ out) {
    int b = blockIdx.y;
    int t = blockIdx.x * TT + threadIdx.x;
    if (t >= TLEN) return;
    const float* pb = g_p4 + b * TLEN;

    float pv[16];
#pragma unroll
    for (int k = 0; k < 16; k++) {
        int tt = t - (15 - k);
        pv[k] = (tt >= 0) ? pb[tt] : 0.f;
    }
    float lin = 0.f;
#pragma unroll
    for (int k = 0; k < 16; k++) lin = fmaf(w1[k], pv[k], lin);

    float x2[6];
#pragma unroll
    for (int j = 0; j < 6; j++) {
        float a = 0.f;
#pragma unroll
        for (int k = 0; k < 16; k++) a = fmaf(w2[j * 16 + k], pv[k], a);
        x2[j] = a;
    }
    float quad = x2[0] * x2[3] + x2[1] * x2[4] + x2[2] * x2[5];
    out[b * TLEN + t] = lin + quad;
}

// ==================== host launch ==========================================
extern "C" void kernel_launch(void* const* d_in, const int* in_sizes, int n_in,
                              void* d_out, int out_size) {
    const float* x       = (const float*)d_in[0];
    const float* conv1_w = (const float*)d_in[1];
    const float* res_w1  = (const float*)d_in[2];
    const float* res_w2  = (const float*)d_in[3];
    const float* post2_w = (const float*)d_in[4];
    const float* post3_w = (const float*)d_in[5];
    const float* post4_w = (const float*)d_in[6];
    const float* vnn1_w  = (const float*)d_in[7];
    const float* vnn2_w  = (const float*)d_in[8];
    float* out = (float*)d_out;

    uint32_t *bh0, *bl0, *bh1, *bl1;
    uint32_t *w1h, *w1l, *w2h, *w2l;
    float *tsp, *p2p, *p3p, *p4p;
    cudaGetSymbolAddress((void**)&bh0, g_bh0);
    cudaGetSymbolAddress((void**)&bl0, g_bl0);
    cudaGetSymbolAddress((void**)&bh1, g_bh1);
    cudaGetSymbolAddress((void**)&bl1, g_bl1);
    cudaGetSymbolAddress((void**)&w1h, g_w1h);
    cudaGetSymbolAddress((void**)&w1l, g_w1l);
    cudaGetSymbolAddress((void**)&w2h, g_w2h);
    cudaGetSymbolAddress((void**)&w2l, g_w2l);
    cudaGetSymbolAddress((void**)&tsp, g_ts);
    cudaGetSymbolAddress((void**)&p2p, g_p2);
    cudaGetSymbolAddress((void**)&p3p, g_p3);
    cudaGetSymbolAddress((void**)&p4p, g_p4);

    cudaFuncSetAttribute(k_layer, cudaFuncAttributeMaxDynamicSharedMemorySize,
                         SMEM_LAYER_BYTES);

    dim3 grid(TLEN / 128, BATCH);   // 250 x 8

    k_wprep<<<10, TT>>>(res_w1, res_w2);
    k_front<<<grid, TT>>>(x, conv1_w);

    const uint32_t *hinH = bh0, *hinL = bl0;
    uint32_t *houtH = bh1, *houtL = bl1;
    for (int s = 0; s < 2; s++) {
        for (int i = 0; i < 10; i++) {
            k_layer<<<grid, TLT, SMEM_LAYER_BYTES>>>(
                hinH, hinL, houtH, houtL,
                w1h + (size_t)i * 64 * 52, w1l + (size_t)i * 64 * 52,
                w2h + (size_t)i * 64 * 20, w2l + (size_t)i * 64 * 20,
                1 << i);
            const uint32_t* th = houtH; const uint32_t* tl = houtL;
            houtH = (uint32_t*)hinH; houtL = (uint32_t*)hinL;
            hinH = th; hinL = tl;
        }
    }

    k_tanhskip<<<grid, TT>>>();
    k_conv3tanh<32, 16><<<grid, TT>>>(tsp, p2p, post2_w);
    k_conv3tanh<16, 8><<<grid, TT>>>(p2p, p3p, post3_w);
    k_conv3tanh<8, 1><<<grid, TT>>>(p3p, p4p, post4_w);
    k_vnn<<<grid, TT>>>(vnn1_w, vnn2_w, out);
}